// round 1
// baseline (speedup 1.0000x reference)
#include <cuda_runtime.h>
#include <cstdint>

#define D_DIM 512
#define B_MAX 2048
#define T_CAP 64

// ---------------- device scratch (static, no runtime alloc) ----------------
__device__ float g_wfast[3 * D_DIM * D_DIM];     // tf32-rounded fast_w_hh
__device__ float g_wslow[3 * D_DIM * D_DIM];     // tf32-rounded slow_w_hh
__device__ float g_wgate[D_DIM * 2 * D_DIM];     // tf32-rounded gate_w
__device__ float g_gif[T_CAP * 3 * D_DIM];       // gi_fast (includes b_ih)
__device__ float g_gis[T_CAP * 3 * D_DIM];       // gi_slow
__device__ float g_zf [B_MAX * D_DIM];           // z_fast (carry, = z_fused)
__device__ float g_zfn[B_MAX * D_DIM];           // z_fast_new
__device__ float g_zs0[B_MAX * D_DIM];           // z_slow ping
__device__ float g_zs1[B_MAX * D_DIM];           // z_slow pong
__device__ float g_ghf[B_MAX * 3 * D_DIM];       // fast gh = h @ Whh^T
__device__ float g_ghs[B_MAX * 3 * D_DIM];       // slow gh
__device__ float g_gpre[B_MAX * D_DIM];          // gate pre-activation

// ---------------- small helpers ----------------
__device__ __forceinline__ uint32_t cvt_tf32(float x) {
    uint32_t u;
    asm("cvt.rna.tf32.f32 %0, %1;" : "=r"(u) : "f"(x));
    return u;
}

__device__ __forceinline__ void mma8(float* c, const uint32_t* a, uint32_t b0, uint32_t b1) {
    asm volatile(
        "mma.sync.aligned.m16n8k8.row.col.f32.tf32.tf32.f32 "
        "{%0,%1,%2,%3}, {%4,%5,%6,%7}, {%8,%9}, {%0,%1,%2,%3};\n"
        : "+f"(c[0]), "+f"(c[1]), "+f"(c[2]), "+f"(c[3])
        : "r"(a[0]), "r"(a[1]), "r"(a[2]), "r"(a[3]), "r"(b0), "r"(b1));
}

__device__ __forceinline__ void cp16(void* s, const void* g) {
    uint32_t sa = (uint32_t)__cvta_generic_to_shared(s);
    asm volatile("cp.async.cg.shared.global [%0], [%1], 16;\n" :: "r"(sa), "l"(g));
}

__device__ __forceinline__ float sigm(float x) { return 1.0f / (1.0f + __expf(-x)); }

// ---------------- tf32 GEMM: C[M,N] = A[M,K] @ W[N,K]^T ----------------
// A is split into A0 (k < splitK) and A1 (k >= splitK), both row stride lda.
// Tile: 128 x TN, 256 threads, warps 4(m) x 2(n), KSTEP=16, cp.async double buffer.
#define TM 128
#define KSTEP 16
#define SSTR 20   // padded smem stride (conflict-free for frag loads)

template<int TN>
__global__ __launch_bounds__(256) void gemm_tf32(
    const float* __restrict__ A0, const float* __restrict__ A1, int splitK, int lda,
    const float* __restrict__ W, int ldw,
    float* __restrict__ C, int ldc, int K)
{
    __shared__ float As[2][TM * SSTR];
    __shared__ float Bs[2][TN * SSTR];

    const int tid  = threadIdx.x;
    const int warp = tid >> 5, lane = tid & 31;
    const int wm0 = (warp & 3) * 32;
    const int wn0 = (warp >> 2) * (TN / 2);
    const int group = lane >> 2, tid4 = lane & 3;
    const int rowBase = blockIdx.x * TM;
    const int colBase = blockIdx.y * TN;

    constexpr int NT = TN / 16;   // n8-tiles per warp
    float acc[2][NT][4];
#pragma unroll
    for (int i = 0; i < 2; i++)
#pragma unroll
        for (int j = 0; j < NT; j++)
#pragma unroll
            for (int k = 0; k < 4; k++) acc[i][j][k] = 0.0f;

    const int ar = tid >> 2;        // A row within 64-row pass
    const int ac = (tid & 3) * 4;   // float4 column offset (0..12)

    auto issue = [&](int kc, int buf) {
        const int kk = kc * KSTEP;
        const float* Abase; int kloc;
        if (kk < splitK) { Abase = A0; kloc = kk; }
        else             { Abase = A1; kloc = kk - splitK; }
#pragma unroll
        for (int p = 0; p < TM / 64; p++) {
            int r = ar + p * 64;
            cp16(&As[buf][r * SSTR + ac],
                 Abase + (size_t)(rowBase + r) * lda + kloc + ac);
        }
#pragma unroll
        for (int p = 0; p < TN / 64; p++) {
            int r = ar + p * 64;
            cp16(&Bs[buf][r * SSTR + ac],
                 W + (size_t)(colBase + r) * ldw + kk + ac);
        }
        asm volatile("cp.async.commit_group;\n" ::);
    };

    const int NK = K / KSTEP;
    issue(0, 0);

    for (int kc = 0; kc < NK; kc++) {
        const int buf = kc & 1;
        if (kc + 1 < NK) {
            issue(kc + 1, buf ^ 1);
            asm volatile("cp.async.wait_group 1;\n" ::);
        } else {
            asm volatile("cp.async.wait_group 0;\n" ::);
        }
        __syncthreads();

#pragma unroll
        for (int k8 = 0; k8 < KSTEP / 8; k8++) {
            const int k0 = k8 * 8;
            uint32_t a[2][4];
#pragma unroll
            for (int i = 0; i < 2; i++) {
                int r = wm0 + i * 16 + group;
                a[i][0] = cvt_tf32(As[buf][ r      * SSTR + k0 + tid4    ]);
                a[i][1] = cvt_tf32(As[buf][(r + 8) * SSTR + k0 + tid4    ]);
                a[i][2] = cvt_tf32(As[buf][ r      * SSTR + k0 + tid4 + 4]);
                a[i][3] = cvt_tf32(As[buf][(r + 8) * SSTR + k0 + tid4 + 4]);
            }
#pragma unroll
            for (int j = 0; j < NT; j++) {
                int n = wn0 + j * 8 + group;
                uint32_t b0 = __float_as_uint(Bs[buf][n * SSTR + k0 + tid4    ]);
                uint32_t b1 = __float_as_uint(Bs[buf][n * SSTR + k0 + tid4 + 4]);
                mma8(acc[0][j], a[0], b0, b1);
                mma8(acc[1][j], a[1], b0, b1);
            }
        }
        __syncthreads();
    }

    // epilogue
#pragma unroll
    for (int i = 0; i < 2; i++) {
        const int r0 = rowBase + wm0 + i * 16 + group;
#pragma unroll
        for (int j = 0; j < NT; j++) {
            const int c0 = colBase + wn0 + j * 8 + tid4 * 2;
            *(float2*)&C[(size_t)r0 * ldc + c0]       = make_float2(acc[i][j][0], acc[i][j][1]);
            *(float2*)&C[(size_t)(r0 + 8) * ldc + c0] = make_float2(acc[i][j][2], acc[i][j][3]);
        }
    }
}

// ---------------- GRU elementwise: h_new = GRU(gi[t], gh, h) ----------------
__global__ void gru_ew(const float* __restrict__ gh, const float* __restrict__ gi,
                       const float* __restrict__ bhh, const float* __restrict__ h,
                       float* __restrict__ hout, int BD)
{
    int i = (blockIdx.x * blockDim.x + threadIdx.x) * 4;
    if (i >= BD) return;
    const int b = i >> 9;
    const int j = i & (D_DIM - 1);
    const size_t base = (size_t)b * (3 * D_DIM) + j;

    float4 g0 = *(const float4*)(gh + base);
    float4 g1 = *(const float4*)(gh + base + D_DIM);
    float4 g2 = *(const float4*)(gh + base + 2 * D_DIM);
    float4 i0 = *(const float4*)(gi + j);
    float4 i1 = *(const float4*)(gi + j + D_DIM);
    float4 i2 = *(const float4*)(gi + j + 2 * D_DIM);
    float4 b0 = *(const float4*)(bhh + j);
    float4 b1 = *(const float4*)(bhh + j + D_DIM);
    float4 b2 = *(const float4*)(bhh + j + 2 * D_DIM);
    float4 hv = *(const float4*)(h + i);

    float4 o;
    {
        float r = sigm(i0.x + g0.x + b0.x);
        float z = sigm(i1.x + g1.x + b1.x);
        float n = tanhf(i2.x + r * (g2.x + b2.x));
        o.x = n + z * (hv.x - n);
    }
    {
        float r = sigm(i0.y + g0.y + b0.y);
        float z = sigm(i1.y + g1.y + b1.y);
        float n = tanhf(i2.y + r * (g2.y + b2.y));
        o.y = n + z * (hv.y - n);
    }
    {
        float r = sigm(i0.z + g0.z + b0.z);
        float z = sigm(i1.z + g1.z + b1.z);
        float n = tanhf(i2.z + r * (g2.z + b2.z));
        o.z = n + z * (hv.z - n);
    }
    {
        float r = sigm(i0.w + g0.w + b0.w);
        float z = sigm(i1.w + g1.w + b1.w);
        float n = tanhf(i2.w + r * (g2.w + b2.w));
        o.w = n + z * (hv.w - n);
    }
    *(float4*)(hout + i) = o;
}

// ---------------- gate + fuse + residual + LayerNorm ----------------
__device__ __forceinline__ float block_sum_128(float v, float* red, int tid) {
#pragma unroll
    for (int o = 16; o > 0; o >>= 1) v += __shfl_xor_sync(0xffffffffu, v, o);
    if ((tid & 31) == 0) red[tid >> 5] = v;
    __syncthreads();
    v = red[0] + red[1] + red[2] + red[3];
    __syncthreads();
    return v;
}

__global__ void gate_fuse_ln(const float* __restrict__ gpre, const float* __restrict__ gateb,
                             const float* __restrict__ zfn, const float* __restrict__ zs,
                             float* __restrict__ zf,
                             const float* __restrict__ gamma, const float* __restrict__ beta,
                             float* __restrict__ out, int t, int T)
{
    __shared__ float red[4];
    const int b = blockIdx.x, tid = threadIdx.x;
    const int j = tid * 4;                // 128 threads * 4 = 512
    const size_t base = (size_t)b * D_DIM + j;

    float4 p  = *(const float4*)(gpre + base);
    float4 gb = *(const float4*)(gateb + j);
    float4 a  = *(const float4*)(zfn + base);
    float4 s  = *(const float4*)(zs + base);
    float4 ho = *(const float4*)(zf + base);

    float f[4];
    { float g = sigm(p.x + gb.x); f[0] = s.x + g * (a.x - s.x) + ho.x; }
    { float g = sigm(p.y + gb.y); f[1] = s.y + g * (a.y - s.y) + ho.y; }
    { float g = sigm(p.z + gb.z); f[2] = s.z + g * (a.z - s.z) + ho.z; }
    { float g = sigm(p.w + gb.w); f[3] = s.w + g * (a.w - s.w) + ho.w; }

    float sum = f[0] + f[1] + f[2] + f[3];
    sum = block_sum_128(sum, red, tid);
    const float mu = sum * (1.0f / D_DIM);

    float sq = 0.0f;
#pragma unroll
    for (int k = 0; k < 4; k++) { float d = f[k] - mu; sq += d * d; }
    sq = block_sum_128(sq, red, tid);
    const float rstd = rsqrtf(sq * (1.0f / D_DIM) + 1e-5f);

    float4 gm = *(const float4*)(gamma + j);
    float4 bt = *(const float4*)(beta + j);
    float4 y;
    y.x = (f[0] - mu) * rstd * gm.x + bt.x;
    y.y = (f[1] - mu) * rstd * gm.y + bt.y;
    y.z = (f[2] - mu) * rstd * gm.z + bt.z;
    y.w = (f[3] - mu) * rstd * gm.w + bt.w;

    *(float4*)(out + ((size_t)b * T + t) * D_DIM + j) = y;
    *(float4*)(zf + base) = y;                   // carry for next step
}

// ---------------- prologue kernels ----------------
__global__ void round_tf32_copy(const float* __restrict__ src, float* __restrict__ dst, int n) {
    int i = (blockIdx.x * blockDim.x + threadIdx.x) * 4;
    for (; i < n; i += gridDim.x * blockDim.x * 4) {
        float4 v = *(const float4*)(src + i);
        v.x = __uint_as_float(cvt_tf32(v.x));
        v.y = __uint_as_float(cvt_tf32(v.y));
        v.z = __uint_as_float(cvt_tf32(v.z));
        v.w = __uint_as_float(cvt_tf32(v.w));
        *(float4*)(dst + i) = v;
    }
}

__global__ void init_state(const float* __restrict__ z, float* __restrict__ zf,
                           float* __restrict__ zs, int n) {
    int i = (blockIdx.x * blockDim.x + threadIdx.x) * 4;
    if (i >= n) return;
    float4 v = *(const float4*)(z + i);
    *(float4*)(zf + i) = v;
    *(float4*)(zs + i) = v;
}

// gi[t][m] = dot(emb[t], w_ih[m]) + b_ih[m], fp32 exact (small, one-time)
__global__ void gi_kernel(const float* __restrict__ emb, const float* __restrict__ w_ih,
                          const float* __restrict__ b_ih, float* __restrict__ gi, int T) {
    const int m = blockIdx.x;           // 0..1535
    const int t = threadIdx.x;          // 0..63
    if (t >= T) return;
    const float4* wr = (const float4*)(w_ih + (size_t)m * D_DIM);
    const float4* er = (const float4*)(emb + (size_t)t * D_DIM);
    float s = 0.0f;
    for (int k = 0; k < D_DIM / 4; k++) {
        float4 w = wr[k], e = er[k];
        s += w.x * e.x + w.y * e.y + w.z * e.z + w.w * e.w;
    }
    gi[(size_t)t * (3 * D_DIM) + m] = s + b_ih[m];
}

// ---------------- host driver ----------------
extern "C" void kernel_launch(void* const* d_in, const int* in_sizes, int n_in,
                              void* d_out, int out_size)
{
    const float* z_init      = (const float*)d_in[0];
    const float* step_embeds = (const float*)d_in[1];
    const float* fast_w_ih   = (const float*)d_in[2];
    const float* fast_w_hh   = (const float*)d_in[3];
    const float* fast_b_ih   = (const float*)d_in[4];
    const float* fast_b_hh   = (const float*)d_in[5];
    const float* slow_w_ih   = (const float*)d_in[6];
    const float* slow_w_hh   = (const float*)d_in[7];
    const float* slow_b_ih   = (const float*)d_in[8];
    const float* slow_b_hh   = (const float*)d_in[9];
    const float* gate_w      = (const float*)d_in[10];
    const float* gate_b      = (const float*)d_in[11];
    const float* ln_gamma    = (const float*)d_in[12];
    const float* ln_beta     = (const float*)d_in[13];
    float* out = (float*)d_out;

    const int B  = in_sizes[0] / D_DIM;       // 2048
    const int T  = out_size / (B * D_DIM);    // num_steps (device scalar unusable here)
    const int BD = B * D_DIM;

    float *wf, *ws, *wg, *gif, *gis, *zf, *zfn, *zsA, *zsB, *ghf, *ghs, *gpre;
    cudaGetSymbolAddress((void**)&wf,  g_wfast);
    cudaGetSymbolAddress((void**)&ws,  g_wslow);
    cudaGetSymbolAddress((void**)&wg,  g_wgate);
    cudaGetSymbolAddress((void**)&gif, g_gif);
    cudaGetSymbolAddress((void**)&gis, g_gis);
    cudaGetSymbolAddress((void**)&zf,  g_zf);
    cudaGetSymbolAddress((void**)&zfn, g_zfn);
    cudaGetSymbolAddress((void**)&zsA, g_zs0);
    cudaGetSymbolAddress((void**)&zsB, g_zs1);
    cudaGetSymbolAddress((void**)&ghf, g_ghf);
    cudaGetSymbolAddress((void**)&ghs, g_ghs);
    cudaGetSymbolAddress((void**)&gpre, g_gpre);
    float* zs[2] = { zsA, zsB };

    // ---- prologue ----
    const int n3 = 3 * D_DIM * D_DIM;
    const int ng = D_DIM * 2 * D_DIM;
    round_tf32_copy<<<(n3 / 4 + 255) / 256, 256>>>(fast_w_hh, wf, n3);
    round_tf32_copy<<<(n3 / 4 + 255) / 256, 256>>>(slow_w_hh, ws, n3);
    round_tf32_copy<<<(ng / 4 + 255) / 256, 256>>>(gate_w, wg, ng);
    init_state<<<(BD / 4 + 255) / 256, 256>>>(z_init, zf, zs[0], BD);
    gi_kernel<<<3 * D_DIM, 64>>>(step_embeds, fast_w_ih, fast_b_ih, gif, T);
    gi_kernel<<<3 * D_DIM, 64>>>(step_embeds, slow_w_ih, slow_b_ih, gis, T);

    const dim3 gFast(B / TM, (3 * D_DIM) / 128);
    const dim3 gGate(B / TM, D_DIM / 64);
    const int ewBlocks = (BD / 4 + 255) / 256;

    int cur = 0;
    for (int t = 0; t < T; t++) {
        const bool even = ((t & 1) == 0);

        // hidden GEMMs
        gemm_tf32<128><<<gFast, 256>>>(zf, zf, D_DIM, D_DIM, wf, D_DIM, ghf, 3 * D_DIM, D_DIM);
        if (even)
            gemm_tf32<128><<<gFast, 256>>>(zs[cur], zs[cur], D_DIM, D_DIM, ws, D_DIM, ghs, 3 * D_DIM, D_DIM);

        // GRU elementwise
        gru_ew<<<ewBlocks, 256>>>(ghf, gif + (size_t)t * 3 * D_DIM, fast_b_hh, zf, zfn, BD);
        int ncur = cur;
        if (even) {
            ncur = cur ^ 1;
            gru_ew<<<ewBlocks, 256>>>(ghs, gis + (size_t)t * 3 * D_DIM, slow_b_hh, zs[cur], zs[ncur], BD);
        }

        // gate GEMM over concat([z_fast_new, z_slow]) via split-A
        gemm_tf32<64><<<gGate, 256>>>(zfn, zs[ncur], D_DIM, D_DIM, wg, 2 * D_DIM, gpre, D_DIM, 2 * D_DIM);

        // fuse + residual + LN, writes out[:, t, :] and carries z_fast
        gate_fuse_ln<<<B, 128>>>(gpre, gate_b, zfn, zs[ncur], zf, ln_gamma, ln_beta, out, t, T);

        cur = ncur;
    }
}

// round 4
// speedup vs baseline: 1.2002x; 1.2002x over previous
#include <cuda_runtime.h>
#include <cstdint>

#define D_DIM 512
#define B_MAX 2048
#define T_CAP 64

// ---------------- device scratch ----------------
__device__ float g_wfast[3 * D_DIM * D_DIM];
__device__ float g_wslow[3 * D_DIM * D_DIM];
__device__ float g_wgate[D_DIM * 2 * D_DIM];
__device__ float g_gif[T_CAP * 3 * D_DIM];
__device__ float g_gis[T_CAP * 3 * D_DIM];
__device__ float g_zf  [B_MAX * D_DIM];
__device__ float g_zfr [B_MAX * D_DIM];
__device__ float g_zfn [B_MAX * D_DIM];
__device__ float g_zfnr[B_MAX * D_DIM];
__device__ float g_zs0 [B_MAX * D_DIM];
__device__ float g_zs0r[B_MAX * D_DIM];
__device__ float g_zs1 [B_MAX * D_DIM];
__device__ float g_zs1r[B_MAX * D_DIM];
__device__ float g_ghf[B_MAX * 3 * D_DIM];
__device__ float g_ghs[B_MAX * 3 * D_DIM];
__device__ float g_gpre[B_MAX * D_DIM];

// ---------------- helpers ----------------
__device__ __forceinline__ uint32_t cvt_tf32(float x) {
    uint32_t u; asm("cvt.rna.tf32.f32 %0, %1;" : "=r"(u) : "f"(x)); return u;
}
__device__ __forceinline__ float sigm(float x) { return 1.0f / (1.0f + __expf(-x)); }

__device__ __forceinline__ void mma8(float* c, const uint32_t* a, uint32_t b0, uint32_t b1) {
    asm volatile(
        "mma.sync.aligned.m16n8k8.row.col.f32.tf32.tf32.f32 "
        "{%0,%1,%2,%3}, {%4,%5,%6,%7}, {%8,%9}, {%0,%1,%2,%3};\n"
        : "+f"(c[0]), "+f"(c[1]), "+f"(c[2]), "+f"(c[3])
        : "r"(a[0]), "r"(a[1]), "r"(a[2]), "r"(a[3]), "r"(b0), "r"(b1));
}

__device__ __forceinline__ void cp16(void* s, const void* g) {
    uint32_t sa = (uint32_t)__cvta_generic_to_shared(s);
    asm volatile("cp.async.cg.shared.global [%0], [%1], 16;\n" :: "r"(sa), "l"(g));
}

// ---------------- tf32 GEMM: C[M,N] = A[M,K] @ W[N,K]^T ----------------
// Tile 128x128, 256 threads (8 warps: 4 m x 2 n), KSTEP=32, double-buffered
// cp.async. Operands must be PRE-ROUNDED to tf32 (no in-loop cvt).
// A split at splitK between A0/A1. blockIdx.z selects pointer set (a / b).
#define TM 128
#define TN 128
#define KC 32
#define SSTR 36                        // padded stride (floats): conflict-free
#define STAGE_FLOATS (TM * SSTR)
#define GEMM_SMEM (4u * STAGE_FLOATS * 4u)   // 2 stages x (A + B)

__global__ __launch_bounds__(256, 2) void gemm_mma(
    const float* __restrict__ A0a, const float* __restrict__ A1a,
    const float* __restrict__ Wa, float* __restrict__ Ca,
    const float* __restrict__ A0b, const float* __restrict__ A1b,
    const float* __restrict__ Wb, float* __restrict__ Cb,
    int splitK, int lda, int ldw, int ldc, int K)
{
    extern __shared__ float smem[];
    float* As = smem;                        // [2][STAGE_FLOATS]
    float* Bs = smem + 2 * STAGE_FLOATS;     // [2][STAGE_FLOATS]

    const int tid  = threadIdx.x;
    const int warp = tid >> 5, lane = tid & 31;
    const int wm0 = (warp & 3) * 32;         // warp m-offset (two m16 tiles)
    const int wn0 = (warp >> 2) * 64;        // warp n-offset (eight n8 tiles)
    const int group = lane >> 2, tid4 = lane & 3;

    const float* A0 = blockIdx.z ? A0b : A0a;
    const float* A1 = blockIdx.z ? A1b : A1a;
    const float* W  = blockIdx.z ? Wb  : Wa;
    float*       C  = blockIdx.z ? Cb  : Ca;
    const int rowBase = blockIdx.x * TM;
    const int colBase = blockIdx.y * TN;

    float acc[2][8][4];
#pragma unroll
    for (int i = 0; i < 2; i++)
#pragma unroll
        for (int j = 0; j < 8; j++)
#pragma unroll
            for (int k = 0; k < 4; k++) acc[i][j][k] = 0.0f;

    auto issue = [&](int ic, int buf) {
        const int kk = ic * KC;
        const float* Ab; int kloc;
        if (kk < splitK) { Ab = A0; kloc = kk; }
        else             { Ab = A1; kloc = kk - splitK; }
        float* as = As + buf * STAGE_FLOATS;
        float* bs = Bs + buf * STAGE_FLOATS;
#pragma unroll
        for (int t = 0; t < 4; t++) {
            const int seg = tid + t * 256;   // 1024 segs of 16B per array
            const int r = seg >> 3, c = (seg & 7) * 4;
            cp16(as + r * SSTR + c, Ab + (size_t)(rowBase + r) * lda + kloc + c);
            cp16(bs + r * SSTR + c, W  + (size_t)(colBase + r) * ldw + kk   + c);
        }
        asm volatile("cp.async.commit_group;\n" ::);
    };

    const int NK = K / KC;
    issue(0, 0);

    for (int ic = 0; ic < NK; ic++) {
        const int buf = ic & 1;
        if (ic + 1 < NK) {
            issue(ic + 1, buf ^ 1);
            asm volatile("cp.async.wait_group 1;\n" ::);
        } else {
            asm volatile("cp.async.wait_group 0;\n" ::);
        }
        __syncthreads();

        const float* as = As + buf * STAGE_FLOATS;
        const float* bs = Bs + buf * STAGE_FLOATS;
#pragma unroll
        for (int k8 = 0; k8 < KC / 8; k8++) {
            const int k0 = k8 * 8;
            uint32_t a[2][4];
#pragma unroll
            for (int i = 0; i < 2; i++) {
                const int r = wm0 + i * 16 + group;
                a[i][0] = __float_as_uint(as[ r      * SSTR + k0 + tid4    ]);
                a[i][1] = __float_as_uint(as[(r + 8) * SSTR + k0 + tid4    ]);
                a[i][2] = __float_as_uint(as[ r      * SSTR + k0 + tid4 + 4]);
                a[i][3] = __float_as_uint(as[(r + 8) * SSTR + k0 + tid4 + 4]);
            }
#pragma unroll
            for (int j = 0; j < 8; j++) {
                const int n = wn0 + j * 8 + group;
                uint32_t b0 = __float_as_uint(bs[n * SSTR + k0 + tid4    ]);
                uint32_t b1 = __float_as_uint(bs[n * SSTR + k0 + tid4 + 4]);
                mma8(acc[0][j], a[0], b0, b1);
                mma8(acc[1][j], a[1], b0, b1);
            }
        }
        __syncthreads();
    }

    // epilogue (standard m16n8 D layout)
#pragma unroll
    for (int i = 0; i < 2; i++) {
        const int r0 = rowBase + wm0 + i * 16 + group;
#pragma unroll
        for (int j = 0; j < 8; j++) {
            const int c0 = colBase + wn0 + j * 8 + tid4 * 2;
            *(float2*)&C[(size_t)r0 * ldc + c0]       = make_float2(acc[i][j][0], acc[i][j][1]);
            *(float2*)&C[(size_t)(r0 + 8) * ldc + c0] = make_float2(acc[i][j][2], acc[i][j][3]);
        }
    }
}

// ---------------- GRU elementwise (fast + optional slow via blockIdx.z) ----------------
__global__ void gru_ew2(const float* __restrict__ ghf, const float* __restrict__ ghs,
                        const float* __restrict__ gif_t, const float* __restrict__ gis_t,
                        const float* __restrict__ fbhh, const float* __restrict__ sbhh,
                        const float* __restrict__ zf, const float* __restrict__ zsc,
                        float* __restrict__ zfn, float* __restrict__ zfnr,
                        float* __restrict__ zsn, float* __restrict__ zsnr, int BD)
{
    const int slow = blockIdx.z;
    const float* gh  = slow ? ghs : ghf;
    const float* gi  = slow ? gis_t : gif_t;
    const float* bhh = slow ? sbhh : fbhh;
    const float* h   = slow ? zsc : zf;
    float* ho  = slow ? zsn : zfn;
    float* hor = slow ? zsnr : zfnr;

    int i = (blockIdx.x * blockDim.x + threadIdx.x) * 4;
    if (i >= BD) return;
    const int b = i >> 9;
    const int j = i & (D_DIM - 1);
    const size_t base = (size_t)b * (3 * D_DIM) + j;

    float4 gA = *(const float4*)(gh + base);
    float4 gB = *(const float4*)(gh + base + D_DIM);
    float4 gC = *(const float4*)(gh + base + 2 * D_DIM);
    float4 iA = *(const float4*)(gi + j);
    float4 iB = *(const float4*)(gi + j + D_DIM);
    float4 iC = *(const float4*)(gi + j + 2 * D_DIM);
    float4 bA = *(const float4*)(bhh + j);
    float4 bB = *(const float4*)(bhh + j + D_DIM);
    float4 bC = *(const float4*)(bhh + j + 2 * D_DIM);
    float4 hv = *(const float4*)(h + i);

    float4 o;
    { float r = sigm(iA.x + gA.x + bA.x); float z = sigm(iB.x + gB.x + bB.x);
      float n = tanhf(iC.x + r * (gC.x + bC.x)); o.x = n + z * (hv.x - n); }
    { float r = sigm(iA.y + gA.y + bA.y); float z = sigm(iB.y + gB.y + bB.y);
      float n = tanhf(iC.y + r * (gC.y + bC.y)); o.y = n + z * (hv.y - n); }
    { float r = sigm(iA.z + gA.z + bA.z); float z = sigm(iB.z + gB.z + bB.z);
      float n = tanhf(iC.z + r * (gC.z + bC.z)); o.z = n + z * (hv.z - n); }
    { float r = sigm(iA.w + gA.w + bA.w); float z = sigm(iB.w + gB.w + bB.w);
      float n = tanhf(iC.w + r * (gC.w + bC.w)); o.w = n + z * (hv.w - n); }

    *(float4*)(ho + i) = o;
    float4 orr;
    orr.x = __uint_as_float(cvt_tf32(o.x));
    orr.y = __uint_as_float(cvt_tf32(o.y));
    orr.z = __uint_as_float(cvt_tf32(o.z));
    orr.w = __uint_as_float(cvt_tf32(o.w));
    *(float4*)(hor + i) = orr;
}

// ---------------- gate + fuse + residual + LayerNorm ----------------
__device__ __forceinline__ float block_sum_128(float v, float* red, int tid) {
#pragma unroll
    for (int o = 16; o > 0; o >>= 1) v += __shfl_xor_sync(0xffffffffu, v, o);
    if ((tid & 31) == 0) red[tid >> 5] = v;
    __syncthreads();
    v = red[0] + red[1] + red[2] + red[3];
    __syncthreads();
    return v;
}

__global__ void gate_fuse_ln(const float* __restrict__ gpre, const float* __restrict__ gateb,
                             const float* __restrict__ zfn, const float* __restrict__ zs,
                             float* __restrict__ zf, float* __restrict__ zfr,
                             const float* __restrict__ gamma, const float* __restrict__ beta,
                             float* __restrict__ out, int t, int T)
{
    __shared__ float red[4];
    const int b = blockIdx.x, tid = threadIdx.x;
    const int j = tid * 4;
    const size_t base = (size_t)b * D_DIM + j;

    float4 p  = *(const float4*)(gpre + base);
    float4 gb = *(const float4*)(gateb + j);
    float4 a  = *(const float4*)(zfn + base);
    float4 s  = *(const float4*)(zs + base);
    float4 ho = *(const float4*)(zf + base);

    float f[4];
    { float g = sigm(p.x + gb.x); f[0] = s.x + g * (a.x - s.x) + ho.x; }
    { float g = sigm(p.y + gb.y); f[1] = s.y + g * (a.y - s.y) + ho.y; }
    { float g = sigm(p.z + gb.z); f[2] = s.z + g * (a.z - s.z) + ho.z; }
    { float g = sigm(p.w + gb.w); f[3] = s.w + g * (a.w - s.w) + ho.w; }

    float sum = f[0] + f[1] + f[2] + f[3];
    sum = block_sum_128(sum, red, tid);
    const float mu = sum * (1.0f / D_DIM);

    float sq = 0.0f;
#pragma unroll
    for (int k = 0; k < 4; k++) { float d = f[k] - mu; sq += d * d; }
    sq = block_sum_128(sq, red, tid);
    const float rstd = rsqrtf(sq * (1.0f / D_DIM) + 1e-5f);

    float4 gm = *(const float4*)(gamma + j);
    float4 bt = *(const float4*)(beta + j);
    float4 y;
    y.x = (f[0] - mu) * rstd * gm.x + bt.x;
    y.y = (f[1] - mu) * rstd * gm.y + bt.y;
    y.z = (f[2] - mu) * rstd * gm.z + bt.z;
    y.w = (f[3] - mu) * rstd * gm.w + bt.w;

    *(float4*)(out + ((size_t)b * T + t) * D_DIM + j) = y;
    *(float4*)(zf + base) = y;
    float4 yr;
    yr.x = __uint_as_float(cvt_tf32(y.x));
    yr.y = __uint_as_float(cvt_tf32(y.y));
    yr.z = __uint_as_float(cvt_tf32(y.z));
    yr.w = __uint_as_float(cvt_tf32(y.w));
    *(float4*)(zfr + base) = yr;
}

// ---------------- prologue kernels ----------------
__global__ void round_tf32_copy(const float* __restrict__ src, float* __restrict__ dst, int n) {
    int i = (blockIdx.x * blockDim.x + threadIdx.x) * 4;
    for (; i < n; i += gridDim.x * blockDim.x * 4) {
        float4 v = *(const float4*)(src + i);
        v.x = __uint_as_float(cvt_tf32(v.x));
        v.y = __uint_as_float(cvt_tf32(v.y));
        v.z = __uint_as_float(cvt_tf32(v.z));
        v.w = __uint_as_float(cvt_tf32(v.w));
        *(float4*)(dst + i) = v;
    }
}

__global__ void init_state(const float* __restrict__ z, float* __restrict__ zf,
                           float* __restrict__ zfr, float* __restrict__ zs,
                           float* __restrict__ zsr, int n) {
    int i = (blockIdx.x * blockDim.x + threadIdx.x) * 4;
    if (i >= n) return;
    float4 v = *(const float4*)(z + i);
    *(float4*)(zf + i) = v;
    *(float4*)(zs + i) = v;
    float4 r;
    r.x = __uint_as_float(cvt_tf32(v.x));
    r.y = __uint_as_float(cvt_tf32(v.y));
    r.z = __uint_as_float(cvt_tf32(v.z));
    r.w = __uint_as_float(cvt_tf32(v.w));
    *(float4*)(zfr + i) = r;
    *(float4*)(zsr + i) = r;
}

__global__ void gi_kernel(const float* __restrict__ emb, const float* __restrict__ w_ih,
                          const float* __restrict__ b_ih, float* __restrict__ gi, int T) {
    const int m = blockIdx.x;
    const int t = threadIdx.x;
    if (t >= T) return;
    const float4* wr = (const float4*)(w_ih + (size_t)m * D_DIM);
    const float4* er = (const float4*)(emb + (size_t)t * D_DIM);
    float s = 0.0f;
    for (int k = 0; k < D_DIM / 4; k++) {
        float4 w = wr[k], e = er[k];
        s += w.x * e.x + w.y * e.y + w.z * e.z + w.w * e.w;
    }
    gi[(size_t)t * (3 * D_DIM) + m] = s + b_ih[m];
}

// ---------------- host driver ----------------
extern "C" void kernel_launch(void* const* d_in, const int* in_sizes, int n_in,
                              void* d_out, int out_size)
{
    const float* z_init      = (const float*)d_in[0];
    const float* step_embeds = (const float*)d_in[1];
    const float* fast_w_ih   = (const float*)d_in[2];
    const float* fast_w_hh   = (const float*)d_in[3];
    const float* fast_b_ih   = (const float*)d_in[4];
    const float* fast_b_hh   = (const float*)d_in[5];
    const float* slow_w_ih   = (const float*)d_in[6];
    const float* slow_w_hh   = (const float*)d_in[7];
    const float* slow_b_ih   = (const float*)d_in[8];
    const float* slow_b_hh   = (const float*)d_in[9];
    const float* gate_w      = (const float*)d_in[10];
    const float* gate_b      = (const float*)d_in[11];
    const float* ln_gamma    = (const float*)d_in[12];
    const float* ln_beta     = (const float*)d_in[13];
    float* out = (float*)d_out;

    const int B  = in_sizes[0] / D_DIM;
    const int T  = out_size / (B * D_DIM);
    const int BD = B * D_DIM;

    float *wf, *ws, *wg, *gif, *gis, *zf, *zfr, *zfn, *zfnr;
    float *zsA, *zsAr, *zsB, *zsBr, *ghf, *ghs, *gpre;
    cudaGetSymbolAddress((void**)&wf,   g_wfast);
    cudaGetSymbolAddress((void**)&ws,   g_wslow);
    cudaGetSymbolAddress((void**)&wg,   g_wgate);
    cudaGetSymbolAddress((void**)&gif,  g_gif);
    cudaGetSymbolAddress((void**)&gis,  g_gis);
    cudaGetSymbolAddress((void**)&zf,   g_zf);
    cudaGetSymbolAddress((void**)&zfr,  g_zfr);
    cudaGetSymbolAddress((void**)&zfn,  g_zfn);
    cudaGetSymbolAddress((void**)&zfnr, g_zfnr);
    cudaGetSymbolAddress((void**)&zsA,  g_zs0);
    cudaGetSymbolAddress((void**)&zsAr, g_zs0r);
    cudaGetSymbolAddress((void**)&zsB,  g_zs1);
    cudaGetSymbolAddress((void**)&zsBr, g_zs1r);
    cudaGetSymbolAddress((void**)&ghf,  g_ghf);
    cudaGetSymbolAddress((void**)&ghs,  g_ghs);
    cudaGetSymbolAddress((void**)&gpre, g_gpre);
    float* zs[2]  = { zsA, zsB };
    float* zsr[2] = { zsAr, zsBr };

    cudaFuncSetAttribute(gemm_mma, cudaFuncAttributeMaxDynamicSharedMemorySize, (int)GEMM_SMEM);

    // ---- prologue ----
    const int n3 = 3 * D_DIM * D_DIM;
    const int ng = D_DIM * 2 * D_DIM;
    round_tf32_copy<<<(n3 / 4 + 255) / 256, 256>>>(fast_w_hh, wf, n3);
    round_tf32_copy<<<(n3 / 4 + 255) / 256, 256>>>(slow_w_hh, ws, n3);
    round_tf32_copy<<<(ng / 4 + 255) / 256, 256>>>(gate_w, wg, ng);
    init_state<<<(BD / 4 + 255) / 256, 256>>>(z_init, zf, zfr, zs[0], zsr[0], BD);
    gi_kernel<<<3 * D_DIM, 64>>>(step_embeds, fast_w_ih, fast_b_ih, gif, T);
    gi_kernel<<<3 * D_DIM, 64>>>(step_embeds, slow_w_ih, slow_b_ih, gis, T);

    const int ewBlocks = (BD / 4 + 255) / 256;

    int cur = 0;
    for (int t = 0; t < T; t++) {
        const bool even = ((t & 1) == 0);

        // hidden GEMMs: z=0 fast, z=1 slow (even steps only)
        {
            dim3 grid(B / TM, (3 * D_DIM) / TN, even ? 2 : 1);
            gemm_mma<<<grid, 256, GEMM_SMEM>>>(
                zfr, zfr, wf, ghf,
                zsr[cur], zsr[cur], ws, ghs,
                1 << 30, D_DIM, D_DIM, 3 * D_DIM, D_DIM);
        }

        // GRU elementwise (fast + optional slow)
        int ncur = even ? (cur ^ 1) : cur;
        {
            dim3 grid(ewBlocks, 1, even ? 2 : 1);
            gru_ew2<<<grid, 256>>>(ghf, ghs,
                                   gif + (size_t)t * 3 * D_DIM, gis + (size_t)t * 3 * D_DIM,
                                   fast_b_hh, slow_b_hh,
                                   zf, zs[cur],
                                   zfn, zfnr, zs[ncur], zsr[ncur], BD);
        }

        // gate GEMM over concat([z_fast_new, z_slow]) via split-A, K=1024
        {
            dim3 grid(B / TM, D_DIM / TN, 1);
            gemm_mma<<<grid, 256, GEMM_SMEM>>>(
                zfnr, zsr[ncur], wg, gpre,
                zfnr, zsr[ncur], wg, gpre,
                D_DIM, D_DIM, 2 * D_DIM, D_DIM, 2 * D_DIM);
        }

        // fuse + residual + LN
        gate_fuse_ln<<<B, 128>>>(gpre, gate_b, zfn, zs[ncur], zf, zfr,
                                 ln_gamma, ln_beta, out, t, T);

        cur = ncur;
    }
}

// round 5
// speedup vs baseline: 2.2179x; 1.8479x over previous
#include <cuda_runtime.h>
#include <cuda_fp16.h>
#include <cstdint>

#define D_DIM 512
#define B_MAX 2048
#define T_CAP 64

// ---------------- device scratch ----------------
__device__ __half g_wfh[3 * D_DIM * D_DIM];      // fp16 fast_w_hh
__device__ __half g_wsh[3 * D_DIM * D_DIM];      // fp16 slow_w_hh
__device__ __half g_wgh[D_DIM * 2 * D_DIM];      // fp16 gate_w
__device__ float  g_gif[T_CAP * 3 * D_DIM];
__device__ float  g_gis[T_CAP * 3 * D_DIM];
__device__ float  g_zf  [B_MAX * D_DIM];
__device__ __half g_zfh [B_MAX * D_DIM];
__device__ float  g_zfn [B_MAX * D_DIM];
__device__ __half g_zfnh[B_MAX * D_DIM];
__device__ float  g_zs0 [B_MAX * D_DIM];
__device__ __half g_zs0h[B_MAX * D_DIM];
__device__ float  g_zs1 [B_MAX * D_DIM];
__device__ __half g_zs1h[B_MAX * D_DIM];
__device__ float  g_ghf[B_MAX * 3 * D_DIM];
__device__ float  g_ghs[B_MAX * 3 * D_DIM];
__device__ float  g_gpre[B_MAX * D_DIM];

// ---------------- helpers ----------------
__device__ __forceinline__ float sigm(float x) { return 1.0f / (1.0f + __expf(-x)); }

__device__ __forceinline__ void mma16(float* c, const uint32_t* a, uint32_t b0, uint32_t b1) {
    asm volatile(
        "mma.sync.aligned.m16n8k16.row.col.f32.f16.f16.f32 "
        "{%0,%1,%2,%3}, {%4,%5,%6,%7}, {%8,%9}, {%0,%1,%2,%3};\n"
        : "+f"(c[0]), "+f"(c[1]), "+f"(c[2]), "+f"(c[3])
        : "r"(a[0]), "r"(a[1]), "r"(a[2]), "r"(a[3]), "r"(b0), "r"(b1));
}

__device__ __forceinline__ void cp16(void* s, const void* g) {
    uint32_t sa = (uint32_t)__cvta_generic_to_shared(s);
    asm volatile("cp.async.cg.shared.global [%0], [%1], 16;\n" :: "r"(sa), "l"(g));
}

// ---------------- fp16 GEMM: C[M,N] = A[M,K] @ W[N,K]^T (fp32 accum) ----------------
// Tile TM_ x 128, 256 threads, KC=64 (fp16), double-buffered cp.async.
// A split at splitK between A0/A1 (both __half). blockIdx.z selects pointer set.
#define TNW 128
#define KC  64
#define SSTRH 72                         // padded smem row stride in halves

template<int TM_>
__global__ __launch_bounds__(256, 2) void gemm_h(
    const __half* __restrict__ A0a, const __half* __restrict__ A1a,
    const __half* __restrict__ Wa, float* __restrict__ Ca,
    const __half* __restrict__ A0b, const __half* __restrict__ A1b,
    const __half* __restrict__ Wb, float* __restrict__ Cb,
    int splitK, int lda, int ldw, int ldc, int K)
{
    constexpr int A_STAGE = TM_ * SSTRH;       // halves
    constexpr int B_STAGE = TNW * SSTRH;
    extern __shared__ __half hsm[];
    __half* As = hsm;                          // [2][A_STAGE]
    __half* Bs = hsm + 2 * A_STAGE;            // [2][B_STAGE]

    const int tid  = threadIdx.x;
    const int warp = tid >> 5, lane = tid & 31;
    // warp layout: TM=128 -> 4m x 2n (wn=64); TM=64 -> 2m x 4n (wn=32)
    constexpr int MW = (TM_ == 128) ? 4 : 2;   // warps along m
    constexpr int NJ = (TM_ == 128) ? 8 : 4;   // n8-tiles per warp
    const int wm0 = (warp % MW) * 32;
    const int wn0 = (warp / MW) * (NJ * 8);
    const int group = lane >> 2, tid4 = lane & 3;

    const __half* A0 = blockIdx.z ? A0b : A0a;
    const __half* A1 = blockIdx.z ? A1b : A1a;
    const __half* W  = blockIdx.z ? Wb  : Wa;
    float*        C  = blockIdx.z ? Cb  : Ca;
    const int rowBase = blockIdx.x * TM_;
    const int colBase = blockIdx.y * TNW;

    float acc[2][NJ][4];
#pragma unroll
    for (int i = 0; i < 2; i++)
#pragma unroll
        for (int j = 0; j < NJ; j++)
#pragma unroll
            for (int k = 0; k < 4; k++) acc[i][j][k] = 0.0f;

    auto issue = [&](int ic, int buf) {
        const int kk = ic * KC;
        const __half* Ab; int kloc;
        if (kk < splitK) { Ab = A0; kloc = kk; }
        else             { Ab = A1; kloc = kk - splitK; }
        __half* as = As + buf * A_STAGE;
        __half* bs = Bs + buf * B_STAGE;
        // A: TM_ rows x 64 halves = TM_*8 16B-segments
#pragma unroll
        for (int t = 0; t < TM_ / 32; t++) {
            const int seg = tid + t * 256;
            const int r = seg >> 3, c = (seg & 7) * 8;
            cp16(as + r * SSTRH + c, Ab + (size_t)(rowBase + r) * lda + kloc + c);
        }
        // B: 128 rows x 64 halves = 1024 segments
#pragma unroll
        for (int t = 0; t < 4; t++) {
            const int seg = tid + t * 256;
            const int r = seg >> 3, c = (seg & 7) * 8;
            cp16(bs + r * SSTRH + c, W + (size_t)(colBase + r) * ldw + kk + c);
        }
        asm volatile("cp.async.commit_group;\n" ::);
    };

    const int NK = K / KC;
    issue(0, 0);

    for (int ic = 0; ic < NK; ic++) {
        const int buf = ic & 1;
        if (ic + 1 < NK) {
            issue(ic + 1, buf ^ 1);
            asm volatile("cp.async.wait_group 1;\n" ::);
        } else {
            asm volatile("cp.async.wait_group 0;\n" ::);
        }
        __syncthreads();

        const __half* as = As + buf * A_STAGE;
        const __half* bs = Bs + buf * B_STAGE;
#pragma unroll
        for (int k16 = 0; k16 < KC / 16; k16++) {
            const int k0 = k16 * 16;
            uint32_t a[2][4];
#pragma unroll
            for (int i = 0; i < 2; i++) {
                const int r = wm0 + i * 16 + group;
                a[i][0] = *(const uint32_t*)&as[ r      * SSTRH + k0 + 2 * tid4    ];
                a[i][1] = *(const uint32_t*)&as[(r + 8) * SSTRH + k0 + 2 * tid4    ];
                a[i][2] = *(const uint32_t*)&as[ r      * SSTRH + k0 + 2 * tid4 + 8];
                a[i][3] = *(const uint32_t*)&as[(r + 8) * SSTRH + k0 + 2 * tid4 + 8];
            }
#pragma unroll
            for (int j = 0; j < NJ; j++) {
                const int n = wn0 + j * 8 + group;
                uint32_t b0 = *(const uint32_t*)&bs[n * SSTRH + k0 + 2 * tid4    ];
                uint32_t b1 = *(const uint32_t*)&bs[n * SSTRH + k0 + 2 * tid4 + 8];
                mma16(acc[0][j], a[0], b0, b1);
                mma16(acc[1][j], a[1], b0, b1);
            }
        }
        __syncthreads();
    }

    // epilogue (m16n8 D layout)
#pragma unroll
    for (int i = 0; i < 2; i++) {
        const int r0 = rowBase + wm0 + i * 16 + group;
#pragma unroll
        for (int j = 0; j < NJ; j++) {
            const int c0 = colBase + wn0 + j * 8 + tid4 * 2;
            *(float2*)&C[(size_t)r0 * ldc + c0]       = make_float2(acc[i][j][0], acc[i][j][1]);
            *(float2*)&C[(size_t)(r0 + 8) * ldc + c0] = make_float2(acc[i][j][2], acc[i][j][3]);
        }
    }
}

// ---------------- GRU elementwise (fast + optional slow via blockIdx.z) ----------------
__global__ void gru_ew2(const float* __restrict__ ghf, const float* __restrict__ ghs,
                        const float* __restrict__ gif_t, const float* __restrict__ gis_t,
                        const float* __restrict__ fbhh, const float* __restrict__ sbhh,
                        const float* __restrict__ zf, const float* __restrict__ zsc,
                        float* __restrict__ zfn, __half* __restrict__ zfnh,
                        float* __restrict__ zsn, __half* __restrict__ zsnh, int BD)
{
    const int slow = blockIdx.z;
    const float* gh  = slow ? ghs : ghf;
    const float* gi  = slow ? gis_t : gif_t;
    const float* bhh = slow ? sbhh : fbhh;
    const float* h   = slow ? zsc : zf;
    float*  ho  = slow ? zsn : zfn;
    __half* hoh = slow ? zsnh : zfnh;

    int i = (blockIdx.x * blockDim.x + threadIdx.x) * 4;
    if (i >= BD) return;
    const int b = i >> 9;
    const int j = i & (D_DIM - 1);
    const size_t base = (size_t)b * (3 * D_DIM) + j;

    float4 gA = *(const float4*)(gh + base);
    float4 gB = *(const float4*)(gh + base + D_DIM);
    float4 gC = *(const float4*)(gh + base + 2 * D_DIM);
    float4 iA = *(const float4*)(gi + j);
    float4 iB = *(const float4*)(gi + j + D_DIM);
    float4 iC = *(const float4*)(gi + j + 2 * D_DIM);
    float4 bA = *(const float4*)(bhh + j);
    float4 bB = *(const float4*)(bhh + j + D_DIM);
    float4 bC = *(const float4*)(bhh + j + 2 * D_DIM);
    float4 hv = *(const float4*)(h + i);

    float4 o;
    { float r = sigm(iA.x + gA.x + bA.x); float z = sigm(iB.x + gB.x + bB.x);
      float n = tanhf(iC.x + r * (gC.x + bC.x)); o.x = n + z * (hv.x - n); }
    { float r = sigm(iA.y + gA.y + bA.y); float z = sigm(iB.y + gB.y + bB.y);
      float n = tanhf(iC.y + r * (gC.y + bC.y)); o.y = n + z * (hv.y - n); }
    { float r = sigm(iA.z + gA.z + bA.z); float z = sigm(iB.z + gB.z + bB.z);
      float n = tanhf(iC.z + r * (gC.z + bC.z)); o.z = n + z * (hv.z - n); }
    { float r = sigm(iA.w + gA.w + bA.w); float z = sigm(iB.w + gB.w + bB.w);
      float n = tanhf(iC.w + r * (gC.w + bC.w)); o.w = n + z * (hv.w - n); }

    *(float4*)(ho + i) = o;
    __half2 h01 = make_half2(__float2half_rn(o.x), __float2half_rn(o.y));
    __half2 h23 = make_half2(__float2half_rn(o.z), __float2half_rn(o.w));
    *(__half2*)(hoh + i)     = h01;
    *(__half2*)(hoh + i + 2) = h23;
}

// ---------------- gate + fuse + residual + LayerNorm ----------------
__device__ __forceinline__ float block_sum_128(float v, float* red, int tid) {
#pragma unroll
    for (int o = 16; o > 0; o >>= 1) v += __shfl_xor_sync(0xffffffffu, v, o);
    if ((tid & 31) == 0) red[tid >> 5] = v;
    __syncthreads();
    v = red[0] + red[1] + red[2] + red[3];
    __syncthreads();
    return v;
}

__global__ void gate_fuse_ln(const float* __restrict__ gpre, const float* __restrict__ gateb,
                             const float* __restrict__ zfn, const float* __restrict__ zs,
                             float* __restrict__ zf, __half* __restrict__ zfh,
                             const float* __restrict__ gamma, const float* __restrict__ beta,
                             float* __restrict__ out, int t, int T)
{
    __shared__ float red[4];
    const int b = blockIdx.x, tid = threadIdx.x;
    const int j = tid * 4;
    const size_t base = (size_t)b * D_DIM + j;

    float4 p  = *(const float4*)(gpre + base);
    float4 gb = *(const float4*)(gateb + j);
    float4 a  = *(const float4*)(zfn + base);
    float4 s  = *(const float4*)(zs + base);
    float4 ho = *(const float4*)(zf + base);

    float f[4];
    { float g = sigm(p.x + gb.x); f[0] = s.x + g * (a.x - s.x) + ho.x; }
    { float g = sigm(p.y + gb.y); f[1] = s.y + g * (a.y - s.y) + ho.y; }
    { float g = sigm(p.z + gb.z); f[2] = s.z + g * (a.z - s.z) + ho.z; }
    { float g = sigm(p.w + gb.w); f[3] = s.w + g * (a.w - s.w) + ho.w; }

    float sum = f[0] + f[1] + f[2] + f[3];
    sum = block_sum_128(sum, red, tid);
    const float mu = sum * (1.0f / D_DIM);

    float sq = 0.0f;
#pragma unroll
    for (int k = 0; k < 4; k++) { float d = f[k] - mu; sq += d * d; }
    sq = block_sum_128(sq, red, tid);
    const float rstd = rsqrtf(sq * (1.0f / D_DIM) + 1e-5f);

    float4 gm = *(const float4*)(gamma + j);
    float4 bt = *(const float4*)(beta + j);
    float4 y;
    y.x = (f[0] - mu) * rstd * gm.x + bt.x;
    y.y = (f[1] - mu) * rstd * gm.y + bt.y;
    y.z = (f[2] - mu) * rstd * gm.z + bt.z;
    y.w = (f[3] - mu) * rstd * gm.w + bt.w;

    *(float4*)(out + ((size_t)b * T + t) * D_DIM + j) = y;
    *(float4*)(zf + base) = y;
    *(__half2*)(zfh + base)     = make_half2(__float2half_rn(y.x), __float2half_rn(y.y));
    *(__half2*)(zfh + base + 2) = make_half2(__float2half_rn(y.z), __float2half_rn(y.w));
}

// ---------------- prologue kernels ----------------
__global__ void round_half_copy(const float* __restrict__ src, __half* __restrict__ dst, int n) {
    int i = (blockIdx.x * blockDim.x + threadIdx.x) * 4;
    for (; i < n; i += gridDim.x * blockDim.x * 4) {
        float4 v = *(const float4*)(src + i);
        *(__half2*)(dst + i)     = make_half2(__float2half_rn(v.x), __float2half_rn(v.y));
        *(__half2*)(dst + i + 2) = make_half2(__float2half_rn(v.z), __float2half_rn(v.w));
    }
}

__global__ void init_state(const float* __restrict__ z, float* __restrict__ zf,
                           __half* __restrict__ zfh, float* __restrict__ zs,
                           __half* __restrict__ zsh, int n) {
    int i = (blockIdx.x * blockDim.x + threadIdx.x) * 4;
    if (i >= n) return;
    float4 v = *(const float4*)(z + i);
    *(float4*)(zf + i) = v;
    *(float4*)(zs + i) = v;
    __half2 h01 = make_half2(__float2half_rn(v.x), __float2half_rn(v.y));
    __half2 h23 = make_half2(__float2half_rn(v.z), __float2half_rn(v.w));
    *(__half2*)(zfh + i)     = h01;
    *(__half2*)(zfh + i + 2) = h23;
    *(__half2*)(zsh + i)     = h01;
    *(__half2*)(zsh + i + 2) = h23;
}

__global__ void gi_kernel(const float* __restrict__ emb, const float* __restrict__ w_ih,
                          const float* __restrict__ b_ih, float* __restrict__ gi, int T) {
    const int m = blockIdx.x;
    const int t = threadIdx.x;
    if (t >= T) return;
    const float4* wr = (const float4*)(w_ih + (size_t)m * D_DIM);
    const float4* er = (const float4*)(emb + (size_t)t * D_DIM);
    float s = 0.0f;
    for (int k = 0; k < D_DIM / 4; k++) {
        float4 w = wr[k], e = er[k];
        s += w.x * e.x + w.y * e.y + w.z * e.z + w.w * e.w;
    }
    gi[(size_t)t * (3 * D_DIM) + m] = s + b_ih[m];
}

// ---------------- host driver ----------------
extern "C" void kernel_launch(void* const* d_in, const int* in_sizes, int n_in,
                              void* d_out, int out_size)
{
    const float* z_init      = (const float*)d_in[0];
    const float* step_embeds = (const float*)d_in[1];
    const float* fast_w_ih   = (const float*)d_in[2];
    const float* fast_w_hh   = (const float*)d_in[3];
    const float* fast_b_ih   = (const float*)d_in[4];
    const float* fast_b_hh   = (const float*)d_in[5];
    const float* slow_w_ih   = (const float*)d_in[6];
    const float* slow_w_hh   = (const float*)d_in[7];
    const float* slow_b_ih   = (const float*)d_in[8];
    const float* slow_b_hh   = (const float*)d_in[9];
    const float* gate_w      = (const float*)d_in[10];
    const float* gate_b      = (const float*)d_in[11];
    const float* ln_gamma    = (const float*)d_in[12];
    const float* ln_beta     = (const float*)d_in[13];
    float* out = (float*)d_out;

    const int B  = in_sizes[0] / D_DIM;
    const int T  = out_size / (B * D_DIM);
    const int BD = B * D_DIM;

    __half *wfh, *wsh, *wgh, *zfh, *zfnh, *zsAh, *zsBh;
    float *gif, *gis, *zf, *zfn, *zsA, *zsB, *ghf, *ghs, *gpre;
    cudaGetSymbolAddress((void**)&wfh,  g_wfh);
    cudaGetSymbolAddress((void**)&wsh,  g_wsh);
    cudaGetSymbolAddress((void**)&wgh,  g_wgh);
    cudaGetSymbolAddress((void**)&gif,  g_gif);
    cudaGetSymbolAddress((void**)&gis,  g_gis);
    cudaGetSymbolAddress((void**)&zf,   g_zf);
    cudaGetSymbolAddress((void**)&zfh,  g_zfh);
    cudaGetSymbolAddress((void**)&zfn,  g_zfn);
    cudaGetSymbolAddress((void**)&zfnh, g_zfnh);
    cudaGetSymbolAddress((void**)&zsA,  g_zs0);
    cudaGetSymbolAddress((void**)&zsAh, g_zs0h);
    cudaGetSymbolAddress((void**)&zsB,  g_zs1);
    cudaGetSymbolAddress((void**)&zsBh, g_zs1h);
    cudaGetSymbolAddress((void**)&ghf,  g_ghf);
    cudaGetSymbolAddress((void**)&ghs,  g_ghs);
    cudaGetSymbolAddress((void**)&gpre, g_gpre);
    float*  zs[2]  = { zsA, zsB };
    __half* zsh[2] = { zsAh, zsBh };

    const int SMEM128 = (2 * 128 + 2 * 128) * SSTRH * 2;   // 73728 B
    const int SMEM64  = (2 * 64  + 2 * 128) * SSTRH * 2;   // 55296 B
    cudaFuncSetAttribute(gemm_h<128>, cudaFuncAttributeMaxDynamicSharedMemorySize, SMEM128);
    cudaFuncSetAttribute(gemm_h<64>,  cudaFuncAttributeMaxDynamicSharedMemorySize, SMEM64);

    // ---- prologue ----
    const int n3 = 3 * D_DIM * D_DIM;
    const int ng = D_DIM * 2 * D_DIM;
    round_half_copy<<<(n3 / 4 + 255) / 256, 256>>>(fast_w_hh, wfh, n3);
    round_half_copy<<<(n3 / 4 + 255) / 256, 256>>>(slow_w_hh, wsh, n3);
    round_half_copy<<<(ng / 4 + 255) / 256, 256>>>(gate_w, wgh, ng);
    init_state<<<(BD / 4 + 255) / 256, 256>>>(z_init, zf, zfh, zs[0], zsh[0], BD);
    gi_kernel<<<3 * D_DIM, 64>>>(step_embeds, fast_w_ih, fast_b_ih, gif, T);
    gi_kernel<<<3 * D_DIM, 64>>>(step_embeds, slow_w_ih, slow_b_ih, gis, T);

    const int ewBlocks = (BD / 4 + 255) / 256;

    int cur = 0;
    for (int t = 0; t < T; t++) {
        const bool even = ((t & 1) == 0);

        // hidden GEMMs: z=0 fast, z=1 slow (even steps only); M=2048,N=1536,K=512
        {
            dim3 grid(B / 128, (3 * D_DIM) / TNW, even ? 2 : 1);
            gemm_h<128><<<grid, 256, SMEM128>>>(
                zfh, zfh, wfh, ghf,
                zsh[cur], zsh[cur], wsh, ghs,
                1 << 30, D_DIM, D_DIM, 3 * D_DIM, D_DIM);
        }

        // GRU elementwise (fast + optional slow)
        int ncur = even ? (cur ^ 1) : cur;
        {
            dim3 grid(ewBlocks, 1, even ? 2 : 1);
            gru_ew2<<<grid, 256>>>(ghf, ghs,
                                   gif + (size_t)t * 3 * D_DIM, gis + (size_t)t * 3 * D_DIM,
                                   fast_b_hh, slow_b_hh,
                                   zf, zs[cur],
                                   zfn, zfnh, zs[ncur], zsh[ncur], BD);
        }

        // gate GEMM: M=2048,N=512,K=1024 over concat (split-A), 64x128 tile
        {
            dim3 grid(B / 64, D_DIM / TNW, 1);
            gemm_h<64><<<grid, 256, SMEM64>>>(
                zfnh, zsh[ncur], wgh, gpre,
                zfnh, zsh[ncur], wgh, gpre,
                D_DIM, D_DIM, 2 * D_DIM, D_DIM, 2 * D_DIM);
        }

        // fuse + residual + LN
        gate_fuse_ln<<<B, 128>>>(gpre, gate_b, zfn, zs[ncur], zf, zfh,
                                 ln_gamma, ln_beta, out, t, T);

        cur = ncur;
    }
}